// round 2
// baseline (speedup 1.0000x reference)
#include <cuda_runtime.h>
#include <math.h>

#define B_SZ 1024
#define T_SZ 100
#define C_SZ 384
#define H_SZ 64
#define M_TOTAL (B_SZ * T_SZ)   // 102400

// scratch for q,k,v projections (device globals: no allocation allowed)
__device__ float g_q[M_TOTAL * H_SZ];
__device__ float g_k[M_TOTAL * H_SZ];
__device__ float g_v[M_TOTAL * H_SZ];

// ---------------------------------------------------------------------------
// Kernel 1: QKV projection GEMM.  out[m][n] = sum_k x[m][k] * W[k][n]
// M = 102400, K = 384, N = 64.  blockIdx.y in {0,1,2} selects Wq/Wk/Wv.
// BM=128, BN=64, BK=16, 256 threads, 8x4 micro-tile per thread.
// ---------------------------------------------------------------------------
constexpr int BM = 128, BN = 64, BK = 16;

__global__ __launch_bounds__(256) void qkv_gemm(
    const float* __restrict__ x,
    const float* __restrict__ Wq,
    const float* __restrict__ Wk,
    const float* __restrict__ Wv)
{
    __shared__ float As[BK][BM + 1];   // k-major, +1 pad
    __shared__ float Bs[BK][BN];

    const int t  = threadIdx.x;
    const int m0 = blockIdx.x * BM;
    const int ty = t >> 4;        // 0..15
    const int tx = t & 15;        // 0..15

    const float* W;
    float* outp;
    if (blockIdx.y == 0)      { W = Wq; outp = g_q; }
    else if (blockIdx.y == 1) { W = Wk; outp = g_k; }
    else                      { W = Wv; outp = g_v; }

    float acc[8][4];
#pragma unroll
    for (int i = 0; i < 8; i++)
#pragma unroll
        for (int j = 0; j < 4; j++) acc[i][j] = 0.f;

    for (int k0 = 0; k0 < C_SZ; k0 += BK) {
        // load A tile: 128 rows x 16 cols = 512 float4, 2 per thread
#pragma unroll
        for (int r = 0; r < 2; r++) {
            int idx = t + 256 * r;
            int row = idx >> 2;
            int q   = idx & 3;
            float4 v4 = *(const float4*)&x[(size_t)(m0 + row) * C_SZ + k0 + q * 4];
            As[q * 4 + 0][row] = v4.x;
            As[q * 4 + 1][row] = v4.y;
            As[q * 4 + 2][row] = v4.z;
            As[q * 4 + 3][row] = v4.w;
        }
        // load B tile: 16 rows x 64 cols = 256 float4, 1 per thread
        {
            int row = t >> 4;
            int q   = t & 15;
            float4 v4 = *(const float4*)&W[(size_t)(k0 + row) * H_SZ + q * 4];
            *(float4*)&Bs[row][q * 4] = v4;
        }
        __syncthreads();

#pragma unroll
        for (int kk = 0; kk < BK; kk++) {
            float a[8];
#pragma unroll
            for (int i = 0; i < 8; i++) a[i] = As[kk][ty + 16 * i];
            float4 b4 = *(const float4*)&Bs[kk][tx * 4];
            float b[4] = {b4.x, b4.y, b4.z, b4.w};
#pragma unroll
            for (int i = 0; i < 8; i++)
#pragma unroll
                for (int j = 0; j < 4; j++)
                    acc[i][j] = fmaf(a[i], b[j], acc[i][j]);
        }
        __syncthreads();
    }

#pragma unroll
    for (int i = 0; i < 8; i++) {
        int m = m0 + ty + 16 * i;
        float4 v4 = {acc[i][0], acc[i][1], acc[i][2], acc[i][3]};
        *(float4*)&outp[(size_t)m * H_SZ + tx * 4] = v4;
    }
}

// ---------------------------------------------------------------------------
// Kernel 2: causal attention per batch.
// One CTA per batch (1024 CTAs), 128 threads = 4 warps.
// q/k/v for the batch staged in smem; one warp per query row;
// warp-shuffle softmax; per-warp p-buffer in smem for the PV product.
// Faithful to source bug: logits *= sqrt(64) = 8.
// ---------------------------------------------------------------------------
#define KV_PAD 68   // stride in floats: 16B-aligned rows, conflict-free float4 reads
#define SMEM_FLOATS (T_SZ * H_SZ + 2 * T_SZ * KV_PAD + 4 * 104)

__global__ __launch_bounds__(128) void attn(float* __restrict__ out)
{
    extern __shared__ float sm[];
    float* qs = sm;                     // [100][64]
    float* ks = qs + T_SZ * H_SZ;       // [100][68]
    float* vs = ks + T_SZ * KV_PAD;     // [100][68]
    float* pb = vs + T_SZ * KV_PAD;     // [4][104]

    const int b    = blockIdx.x;
    const int t    = threadIdx.x;
    const int warp = t >> 5;
    const int lane = t & 31;

    const size_t base = (size_t)b * T_SZ * H_SZ;

    for (int i = t; i < T_SZ * H_SZ; i += 128) {
        int row = i >> 6;
        int h   = i & 63;
        qs[i]                 = g_q[base + i];
        ks[row * KV_PAD + h]  = g_k[base + i];
        vs[row * KV_PAD + h]  = g_v[base + i];
    }
    __syncthreads();

    float* p = pb + warp * 104;

    for (int tr = warp; tr < T_SZ; tr += 4) {
        // --- scores: lane handles j = lane + 32*jj ---
        float s[4] = {0.f, 0.f, 0.f, 0.f};
#pragma unroll
        for (int u = 0; u < 16; u++) {
            float4 q4 = *(const float4*)&qs[tr * 64 + u * 4];   // broadcast
#pragma unroll
            for (int jj = 0; jj < 4; jj++) {
                int j  = lane + 32 * jj;
                int jc = (j < T_SZ) ? j : (T_SZ - 1);           // clamp for safe load
                float4 k4 = *(const float4*)&ks[jc * KV_PAD + u * 4];
                s[jj] = fmaf(q4.x, k4.x,
                        fmaf(q4.y, k4.y,
                        fmaf(q4.z, k4.z,
                        fmaf(q4.w, k4.w, s[jj]))));
            }
        }
        // --- scale, causal mask, softmax (warp-level) ---
        float m = -INFINITY;
#pragma unroll
        for (int jj = 0; jj < 4; jj++) {
            int j = lane + 32 * jj;
            s[jj] = (j <= tr) ? s[jj] * 8.0f : -INFINITY;
            m = fmaxf(m, s[jj]);
        }
#pragma unroll
        for (int o = 16; o > 0; o >>= 1)
            m = fmaxf(m, __shfl_xor_sync(0xffffffffu, m, o));

        float sum = 0.f;
#pragma unroll
        for (int jj = 0; jj < 4; jj++) {
            int j   = lane + 32 * jj;
            float e = (j <= tr) ? __expf(s[jj] - m) : 0.f;
            s[jj] = e;
            sum  += e;
        }
#pragma unroll
        for (int o = 16; o > 0; o >>= 1)
            sum += __shfl_xor_sync(0xffffffffu, sum, o);

        float inv = 1.0f / sum;
#pragma unroll
        for (int jj = 0; jj < 4; jj++) {
            int j = lane + 32 * jj;
            if (j < T_SZ) p[j] = s[jj] * inv;
        }
        __syncwarp();

        // --- output: lane handles h = lane and lane+32 ---
        float a0 = 0.f, a1 = 0.f;
        for (int j = 0; j <= tr; j++) {
            float pj = p[j];
            a0 = fmaf(pj, vs[j * KV_PAD + lane],      a0);
            a1 = fmaf(pj, vs[j * KV_PAD + lane + 32], a1);
        }
        out[base + (size_t)tr * H_SZ + lane]      = a0;
        out[base + (size_t)tr * H_SZ + lane + 32] = a1;
        __syncwarp();   // protect p before next row's writes
    }
}

// ---------------------------------------------------------------------------
extern "C" void kernel_launch(void* const* d_in, const int* in_sizes, int n_in,
                              void* d_out, int out_size)
{
    const float* x  = (const float*)d_in[0];
    const float* Wq = (const float*)d_in[1];
    const float* Wk = (const float*)d_in[2];
    const float* Wv = (const float*)d_in[3];
    float* out = (float*)d_out;

    // QKV projections: grid (102400/128, 3)
    dim3 ggrid(M_TOTAL / BM, 3);
    qkv_gemm<<<ggrid, 256>>>(x, Wq, Wk, Wv);

    // Attention: one CTA per batch.  cudaFuncSetAttribute is not a
    // stream-ordered API (graph-capture safe) and is idempotent.
    const int smem_bytes = SMEM_FLOATS * sizeof(float);
    cudaFuncSetAttribute(attn, cudaFuncAttributeMaxDynamicSharedMemorySize, smem_bytes);
    attn<<<B_SZ, 128, smem_bytes>>>(out);
}

// round 4
// speedup vs baseline: 1.6304x; 1.6304x over previous
#include <cuda_runtime.h>
#include <math.h>
#include <stdint.h>

#define B_SZ 1024
#define T_SZ 100
#define C_SZ 384
#define H_SZ 64
#define M_TOTAL (B_SZ * T_SZ)   // 102400

// scratch (device globals: no allocation allowed)
__device__ float g_q[M_TOTAL * H_SZ];
__device__ float g_k[M_TOTAL * H_SZ];
__device__ float g_v[M_TOTAL * H_SZ];

// W in hi/lo tf32 fragment-major layout: [mat(3)][ktG(48)][nt(8)][var(2)][reg(2)][lane(32)]
#define KTG 48
__device__ float g_wfrag[3 * KTG * 8 * 2 * 2 * 32];   // 589KB

// ---------------------------------------------------------------------------
// helpers
// ---------------------------------------------------------------------------
__device__ __forceinline__ uint32_t f2tf32(float x) {
    uint32_t u;
    asm("cvt.rna.tf32.f32 %0, %1;" : "=r"(u) : "f"(x));
    return u;
}

__device__ __forceinline__ void mma_tf32(float* d, const uint32_t* a, const uint32_t* b) {
    asm volatile(
        "mma.sync.aligned.m16n8k8.row.col.f32.tf32.tf32.f32 "
        "{%0,%1,%2,%3}, {%4,%5,%6,%7}, {%8,%9}, {%0,%1,%2,%3};"
        : "+f"(d[0]), "+f"(d[1]), "+f"(d[2]), "+f"(d[3])
        : "r"(a[0]), "r"(a[1]), "r"(a[2]), "r"(a[3]), "r"(b[0]), "r"(b[1]));
}

// ---------------------------------------------------------------------------
// Kernel 0: split W into tf32 hi/lo, fragment-major layout (runs every call,
// ~3us).  thread -> (mat, ktG, nt, reg, lane); writes var 0 (hi) and 1 (lo).
// frag value: k = ktG*8 + reg*4 + lane%4 ; n = nt*8 + lane/4
// ---------------------------------------------------------------------------
__global__ void wsplit(const float* __restrict__ Wq,
                       const float* __restrict__ Wk,
                       const float* __restrict__ Wv)
{
    int i = blockIdx.x * blockDim.x + threadIdx.x;
    if (i >= 3 * KTG * 8 * 2 * 32) return;
    int mat  = i / (KTG * 8 * 2 * 32);
    int rem  = i % (KTG * 8 * 2 * 32);
    int kt   = rem / (8 * 2 * 32);
    int rem2 = rem % (8 * 2 * 32);
    int nt   = rem2 / 64;
    int rem3 = rem2 % 64;
    int reg  = rem3 / 32;
    int lane = rem3 % 32;

    int k = kt * 8 + reg * 4 + (lane % 4);
    int n = nt * 8 + (lane / 4);
    const float* W = (mat == 0) ? Wq : (mat == 1) ? Wk : Wv;
    float w = W[k * H_SZ + n];

    uint32_t hi = f2tf32(w);
    uint32_t lo = f2tf32(w - __uint_as_float(hi));

    int base = ((mat * KTG + kt) * 8 + nt) * 128 + reg * 32 + lane;
    g_wfrag[base]      = __uint_as_float(hi);   // var 0
    g_wfrag[base + 64] = __uint_as_float(lo);   // var 1
}

// ---------------------------------------------------------------------------
// Kernel 1: QKV projection GEMM via 3xTF32 mma.sync.
// out[m][n] = sum_k x[m][k] * W[k][n].  M=102400, K=384, N=64.
// BM=128, BN=64, BK=32.  256 threads = 8 warps (4 m x 2 n); warp tile 32x32.
// A staged fp32 in fragment-major smem; hi/lo split done in registers.
// ---------------------------------------------------------------------------
constexpr int BM = 128, BK = 32;

__global__ __launch_bounds__(256) void qkv_gemm_tc(const float* __restrict__ x)
{
    __shared__ float sA[4 * 8 * 4 * 32];          // [kt][mt][reg][lane] 16KB fp32
    __shared__ float sB[4 * 8 * 2 * 2 * 32];      // [kt][nt][var][reg][lane] 16KB

    const int t    = threadIdx.x;
    const int l    = t & 31;
    const int w    = t >> 5;
    const int wm   = w & 3;       // m-warp 0..3 (32 rows each)
    const int wn   = w >> 2;      // n-warp 0..1 (32 cols each)
    const int m0   = blockIdx.x * BM;
    const int mat  = blockIdx.y;

    const float* wfrag = g_wfrag + mat * (KTG * 8 * 128);

    // A-load assignment: row = t/2, half = t%2 -> 16 consecutive k (4 float4)
    const int arow  = t >> 1;
    const int ahalf = t & 1;
    const int rr    = arow & 15;      // row within 16-tile
    const int amt   = arow >> 4;      // m-tile 0..7

    float acc[2][4][4];
#pragma unroll
    for (int i = 0; i < 2; i++)
#pragma unroll
        for (int j = 0; j < 4; j++)
#pragma unroll
            for (int c = 0; c < 4; c++) acc[i][j][c] = 0.f;

    float4 av[4], bv[4];
    // prologue loads for iter 0
    {
        const float* asrc = &x[(size_t)(m0 + arow) * C_SZ + ahalf * 16];
#pragma unroll
        for (int i = 0; i < 4; i++) av[i] = *(const float4*)&asrc[i * 4];
        const float4* bsrc = (const float4*)(wfrag + 0);
#pragma unroll
        for (int i = 0; i < 4; i++) bv[i] = bsrc[t + 256 * i];
    }

    for (int it = 0; it < C_SZ / BK; it++) {
        __syncthreads();   // previous iter's smem reads done

        // --- store A into fragment layout (STS.128, 4-phase floor) ---
#pragma unroll
        for (int ktl = 0; ktl < 2; ktl++) {
            int kt = ahalf * 2 + ktl;
#pragma unroll
            for (int cv = 0; cv < 2; cv++) {
                int reg = (rr >> 3) + 2 * cv;
                float* dst = &sA[((kt * 8 + amt) * 4 + reg) * 32 + (rr & 7) * 4];
                *(float4*)dst = av[ktl * 2 + cv];
            }
        }
        // --- store B slice linearly ---
        {
            float4* bdst = (float4*)sB;
#pragma unroll
            for (int i = 0; i < 4; i++) bdst[t + 256 * i] = bv[i];
        }
        __syncthreads();

        // --- prefetch next iter's tiles (hidden under compute) ---
        if (it + 1 < C_SZ / BK) {
            const float* asrc = &x[(size_t)(m0 + arow) * C_SZ + (it + 1) * BK + ahalf * 16];
#pragma unroll
            for (int i = 0; i < 4; i++) av[i] = *(const float4*)&asrc[i * 4];
            const float4* bsrc = (const float4*)(wfrag + (size_t)(it + 1) * 4 * 1024);
#pragma unroll
            for (int i = 0; i < 4; i++) bv[i] = bsrc[t + 256 * i];
        }

        // --- compute ---
#pragma unroll
        for (int kt = 0; kt < 4; kt++) {
            uint32_t ah[2][4], al[2][4];
#pragma unroll
            for (int mt2 = 0; mt2 < 2; mt2++) {
                int mt = wm * 2 + mt2;
                const float* src = &sA[(kt * 8 + mt) * 128 + l];
#pragma unroll
                for (int r = 0; r < 4; r++) {
                    float a = src[r * 32];
                    ah[mt2][r] = f2tf32(a);
                    al[mt2][r] = f2tf32(a - __uint_as_float(ah[mt2][r]));
                }
            }
#pragma unroll
            for (int nt2 = 0; nt2 < 4; nt2++) {
                int nt = wn * 4 + nt2;
                const float* bs = &sB[(kt * 8 + nt) * 128 + l];
                uint32_t bh[2], bl[2];
                bh[0] = __float_as_uint(bs[0]);
                bh[1] = __float_as_uint(bs[32]);
                bl[0] = __float_as_uint(bs[64]);
                bl[1] = __float_as_uint(bs[96]);
#pragma unroll
                for (int mt2 = 0; mt2 < 2; mt2++) {
                    mma_tf32(acc[mt2][nt2], al[mt2], bh);   // small terms first
                    mma_tf32(acc[mt2][nt2], ah[mt2], bl);
                    mma_tf32(acc[mt2][nt2], ah[mt2], bh);
                }
            }
        }
    }

    // --- epilogue ---
    float* outp = (mat == 0) ? g_q : (mat == 1) ? g_k : g_v;
#pragma unroll
    for (int mt2 = 0; mt2 < 2; mt2++) {
#pragma unroll
        for (int nt2 = 0; nt2 < 4; nt2++) {
            int mrow = m0 + wm * 32 + mt2 * 16 + (l >> 2);
            int col  = wn * 32 + nt2 * 8 + (l & 3) * 2;
            float2 v0 = {acc[mt2][nt2][0], acc[mt2][nt2][1]};
            float2 v1 = {acc[mt2][nt2][2], acc[mt2][nt2][3]};
            *(float2*)&outp[(size_t)mrow * H_SZ + col]       = v0;
            *(float2*)&outp[(size_t)(mrow + 8) * H_SZ + col] = v1;
        }
    }
}

// ---------------------------------------------------------------------------
// Kernel 2: causal attention.  One CTA per batch, 256 threads = 8 warps.
// Each warp processes 4 query rows at a time (register-blocked): k/v shared
// loads amortized 4x.  Warp-shuffle softmax; per-warp p buffers in smem.
// Faithful to source bug: logits *= sqrt(64) = 8.
// ---------------------------------------------------------------------------
#define KV_PAD 68
#define NQUAD 25   // 100 rows / 4
#define SMEM_FLOATS (T_SZ * H_SZ + 2 * T_SZ * KV_PAD + 8 * 4 * 104)

__global__ __launch_bounds__(256) void attn(float* __restrict__ out)
{
    extern __shared__ float sm[];
    float* qs = sm;                     // [100][64]
    float* ks = qs + T_SZ * H_SZ;       // [100][68]
    float* vs = ks + T_SZ * KV_PAD;     // [100][68]
    float* pb = vs + T_SZ * KV_PAD;     // [8][4][104]

    const int b    = blockIdx.x;
    const int t    = threadIdx.x;
    const int warp = t >> 5;
    const int lane = t & 31;

    const size_t base = (size_t)b * T_SZ * H_SZ;

    for (int i = t; i < T_SZ * H_SZ; i += 256) {
        int row = i >> 6;
        int h   = i & 63;
        qs[i]                = g_q[base + i];
        ks[row * KV_PAD + h] = g_k[base + i];
        vs[row * KV_PAD + h] = g_v[base + i];
    }
    __syncthreads();

    float* p = pb + warp * 4 * 104;

    for (int q4 = warp; q4 < NQUAD; q4 += 8) {
        const int tr0 = q4 * 4;

        // --- scores: 4 rows x 4 j-strips ---
        float s[4][4];
#pragma unroll
        for (int r = 0; r < 4; r++)
#pragma unroll
            for (int jj = 0; jj < 4; jj++) s[r][jj] = 0.f;

#pragma unroll
        for (int u = 0; u < 16; u++) {
            float4 q4v[4];
#pragma unroll
            for (int r = 0; r < 4; r++)
                q4v[r] = *(const float4*)&qs[(tr0 + r) * 64 + u * 4];  // broadcast
#pragma unroll
            for (int jj = 0; jj < 4; jj++) {
                int j  = lane + 32 * jj;
                int jc = (j < T_SZ) ? j : (T_SZ - 1);
                float4 k4 = *(const float4*)&ks[jc * KV_PAD + u * 4];
#pragma unroll
                for (int r = 0; r < 4; r++) {
                    s[r][jj] = fmaf(q4v[r].x, k4.x,
                               fmaf(q4v[r].y, k4.y,
                               fmaf(q4v[r].z, k4.z,
                               fmaf(q4v[r].w, k4.w, s[r][jj]))));
                }
            }
        }

        // --- per-row softmax (warp-level) ---
#pragma unroll
        for (int r = 0; r < 4; r++) {
            const int tr = tr0 + r;
            float m = -INFINITY;
#pragma unroll
            for (int jj = 0; jj < 4; jj++) {
                int j = lane + 32 * jj;
                s[r][jj] = (j <= tr) ? s[r][jj] * 8.0f : -INFINITY;
                m = fmaxf(m, s[r][jj]);
            }
#pragma unroll
            for (int o = 16; o > 0; o >>= 1)
                m = fmaxf(m, __shfl_xor_sync(0xffffffffu, m, o));

            float sum = 0.f;
#pragma unroll
            for (int jj = 0; jj < 4; jj++) {
                int j   = lane + 32 * jj;
                float e = (j <= tr) ? __expf(s[r][jj] - m) : 0.f;
                s[r][jj] = e;
                sum += e;
            }
#pragma unroll
            for (int o = 16; o > 0; o >>= 1)
                sum += __shfl_xor_sync(0xffffffffu, sum, o);

            float inv = 1.0f / sum;
#pragma unroll
            for (int jj = 0; jj < 4; jj++) {
                int j = lane + 32 * jj;
                if (j < T_SZ) p[r * 104 + j] = s[r][jj] * inv;   // 0 beyond tr
            }
        }
        __syncwarp();

        // --- PV: 4 rows, lane handles h = lane, lane+32 ---
        float a[4][2];
#pragma unroll
        for (int r = 0; r < 4; r++) { a[r][0] = 0.f; a[r][1] = 0.f; }

        for (int j = 0; j < tr0 + 4; j++) {
            float v0 = vs[j * KV_PAD + lane];
            float v1 = vs[j * KV_PAD + lane + 32];
#pragma unroll
            for (int r = 0; r < 4; r++) {
                float pj = p[r * 104 + j];   // broadcast; 0 if masked
                a[r][0] = fmaf(pj, v0, a[r][0]);
                a[r][1] = fmaf(pj, v1, a[r][1]);
            }
        }
#pragma unroll
        for (int r = 0; r < 4; r++) {
            out[base + (size_t)(tr0 + r) * H_SZ + lane]      = a[r][0];
            out[base + (size_t)(tr0 + r) * H_SZ + lane + 32] = a[r][1];
        }
        __syncwarp();
    }
}

// ---------------------------------------------------------------------------
extern "C" void kernel_launch(void* const* d_in, const int* in_sizes, int n_in,
                              void* d_out, int out_size)
{
    const float* x  = (const float*)d_in[0];
    const float* Wq = (const float*)d_in[1];
    const float* Wk = (const float*)d_in[2];
    const float* Wv = (const float*)d_in[3];
    float* out = (float*)d_out;

    // 0) split W into tf32 hi/lo fragments
    wsplit<<<(3 * KTG * 8 * 2 * 32 + 255) / 256, 256>>>(Wq, Wk, Wv);

    // 1) QKV projections: grid (800, 3)
    dim3 ggrid(M_TOTAL / BM, 3);
    qkv_gemm_tc<<<ggrid, 256>>>(x);

    // 2) attention: one CTA per batch
    const int smem_bytes = SMEM_FLOATS * sizeof(float);
    cudaFuncSetAttribute(attn, cudaFuncAttributeMaxDynamicSharedMemorySize, smem_bytes);
    attn<<<B_SZ, 256, smem_bytes>>>(out);
}